// round 5
// baseline (speedup 1.0000x reference)
#include <cuda_runtime.h>
#include <cstdint>

#define N_NODES 100000
#define KNBR 32
#define IN_C 128
#define OUT_C 64
#define NODES_PER_BLK 4

// scratch for h = x @ W^T  [N, 64]
__device__ float g_h[(size_t)N_NODES * OUT_C];
// 1 if nbrs is stored as int64, 0 if int32
__device__ int g_is64;

// ---------------------------------------------------------------------------
// Kernel 0: detect nbrs dtype. Values are node indices in [0, 100000), so if
// storage is int64 (little-endian), every odd 32-bit word is 0. With int32
// storage, 32 consecutive random indices all being zero is ~impossible.
// ---------------------------------------------------------------------------
__global__ void detect_kernel(const int* __restrict__ nbrs32) {
    int orv = 0;
#pragma unroll
    for (int i = 1; i < 64; i += 2) orv |= nbrs32[i];
    g_is64 = (orv == 0) ? 1 : 0;
}

// ---------------------------------------------------------------------------
// Kernel 1: h[n][c] = sum_k x[n][k] * W[c][k]
// One thread per node, 64 accumulators, W transposed in shared memory.
// ---------------------------------------------------------------------------
__global__ void __launch_bounds__(256) gemm_kernel(const float* __restrict__ x,
                                                   const float* __restrict__ W) {
    // Ws[k][c] with row pitch 68 floats (272B rows, 16B-aligned)
    __shared__ float Ws[128 * 68];
    int tid = threadIdx.x;

    // Load W [64][128] row-major -> transposed smem
    for (int i = tid; i < OUT_C * IN_C; i += 256) {
        int c = i >> 7;        // 0..63
        int k = i & 127;       // 0..127
        Ws[k * 68 + c] = W[i];
    }
    __syncthreads();

    int n = blockIdx.x * 256 + tid;
    if (n >= N_NODES) return;

    float4 acc[16];
#pragma unroll
    for (int i = 0; i < 16; i++) acc[i] = make_float4(0.f, 0.f, 0.f, 0.f);

    const float4* xr = reinterpret_cast<const float4*>(x + (size_t)n * IN_C);

#pragma unroll
    for (int kt = 0; kt < 8; ++kt) {
        float4 xc[4];
#pragma unroll
        for (int i = 0; i < 4; i++) xc[i] = xr[kt * 4 + i];
        const float* xs = reinterpret_cast<const float*>(xc);
#pragma unroll
        for (int kk = 0; kk < 16; ++kk) {
            float xv = xs[kk];
            const float4* wr =
                reinterpret_cast<const float4*>(Ws + (kt * 16 + kk) * 68);
#pragma unroll
            for (int i = 0; i < 16; i++) {
                float4 w = wr[i];
                acc[i].x = fmaf(xv, w.x, acc[i].x);
                acc[i].y = fmaf(xv, w.y, acc[i].y);
                acc[i].z = fmaf(xv, w.z, acc[i].z);
                acc[i].w = fmaf(xv, w.w, acc[i].w);
            }
        }
    }

    float4* ho = reinterpret_cast<float4*>(g_h + (size_t)n * OUT_C);
#pragma unroll
    for (int i = 0; i < 16; i++) ho[i] = acc[i];
}

// ---------------------------------------------------------------------------
// Kernel 2: one thread = one (node, channel). Gather the node's 32 neighbor
// rows of h into smem (coalesced float4), then each thread loads its channel
// column into registers and runs a fully-unrolled Batcher odd-even mergesort
// (n=32). Output v[15] = lower median. ptxas prunes CEs not feeding v[15].
// Block = 256 threads = 4 nodes x 64 channels.
// ---------------------------------------------------------------------------
__global__ void __launch_bounds__(256) median_kernel(const void* __restrict__ nbrs,
                                                     float* __restrict__ out) {
    __shared__ float tile[NODES_PER_BLK][KNBR * OUT_C];  // 4 x 8KB
    __shared__ int idx_s[NODES_PER_BLK][KNBR];

    const int tid = threadIdx.x;
    const int w = tid >> 6;       // node slot 0..3
    const int sub = tid & 63;     // 0..63 within node group
    const size_t node = (size_t)blockIdx.x * NODES_PER_BLK + w;

    // load this node's 32 neighbor indices (dtype decided at runtime)
    if (sub < KNBR) {
        long long nb;
        if (g_is64) {
            nb = reinterpret_cast<const long long*>(nbrs)[node * KNBR + sub];
        } else {
            nb = (long long)reinterpret_cast<const int*>(nbrs)[node * KNBR + sub];
        }
        idx_s[w][sub] = (int)nb;
    }
    __syncthreads();

    // cooperative gather: 32 rows x 16 float4 = 512 float4 per node,
    // 8 per thread; 16 consecutive lanes load one 256B row -> coalesced.
    const float4* h4 = reinterpret_cast<const float4*>(g_h);
    float4* t4 = reinterpret_cast<float4*>(tile[w]);
#pragma unroll
    for (int s = 0; s < 8; ++s) {
        int linear = s * 64 + sub;
        int r = linear >> 4;       // row 0..31
        int c4 = linear & 15;      // float4 slot
        int row = idx_s[w][r];
        t4[r * 16 + c4] = h4[(size_t)row * 16 + c4];
    }
    __syncthreads();

    // column load: lane c reads tile[w][j*64 + c] -> conflict-free
    const int c = sub;
    float v[KNBR];
#pragma unroll
    for (int j = 0; j < KNBR; ++j) v[j] = tile[w][j * OUT_C + c];

    // Batcher odd-even mergesort, n = 32, fully unrolled (constant indices)
#pragma unroll
    for (int p = 1; p < 32; p <<= 1) {
#pragma unroll
        for (int k = p; k >= 1; k >>= 1) {
#pragma unroll
            for (int j = (k & (p - 1)); j + k < 32; j += 2 * k) {
#pragma unroll
                for (int i = 0; i < k; ++i) {
                    if (i + j + k < 32) {
                        if ((i + j) / (2 * p) == (i + j + k) / (2 * p)) {
                            float a = v[i + j];
                            float b = v[i + j + k];
                            v[i + j] = fminf(a, b);
                            v[i + j + k] = fmaxf(a, b);
                        }
                    }
                }
            }
        }
    }

    // lower median = index 15 of ascending sort; coalesced store
    out[node * OUT_C + c] = v[15];
}

// ---------------------------------------------------------------------------
extern "C" void kernel_launch(void* const* d_in, const int* in_sizes, int n_in,
                              void* d_out, int out_size) {
    // Identify inputs by element count (all three are distinct):
    //   x    : 100000*128 = 12,800,000 f32
    //   W    : 64*128     = 8,192      f32
    //   nbrs : 100000*32  = 3,200,000  (i32 or i64) -- whatever remains
    const float* x = nullptr;
    const float* W = nullptr;
    const void*  nbrs = nullptr;
    for (int i = 0; i < n_in; ++i) {
        if (in_sizes[i] == N_NODES * IN_C)      x = (const float*)d_in[i];
        else if (in_sizes[i] == OUT_C * IN_C)   W = (const float*)d_in[i];
        else                                    nbrs = d_in[i];
    }
    float* out = (float*)d_out;  // [100000, 64] f32

    detect_kernel<<<1, 1>>>((const int*)nbrs);
    gemm_kernel<<<(N_NODES + 255) / 256, 256>>>(x, W);
    median_kernel<<<N_NODES / NODES_PER_BLK, 256>>>(nbrs, out);
}

// round 11
// speedup vs baseline: 3.1255x; 3.1255x over previous
#include <cuda_runtime.h>
#include <cstdint>

#define N_NODES 100000
#define KNBR 32
#define IN_C 128
#define OUT_C 64
#define NODES_PER_BLK 4

// scratch for h = x @ W^T  [N, 64]
__device__ float g_h[(size_t)N_NODES * OUT_C];
// 1 if nbrs is stored as int64, 0 if int32
__device__ int g_is64;

// ---------------------------------------------------------------------------
// Kernel 1: h[n][c] = sum_k x[n][k] * W[c][k]
// One thread per node, 64 accumulators, W transposed in shared memory.
// Block 0 / thread 0 also sniffs the nbrs dtype (indices < 100000 => if
// storage is int64 little-endian, all odd 32-bit words are zero).
// ---------------------------------------------------------------------------
__global__ void __launch_bounds__(256) gemm_kernel(const float* __restrict__ x,
                                                   const float* __restrict__ W,
                                                   const int* __restrict__ nbrs32) {
    if (blockIdx.x == 0 && threadIdx.x == 0) {
        int orv = 0;
#pragma unroll
        for (int i = 1; i < 64; i += 2) orv |= nbrs32[i];
        g_is64 = (orv == 0) ? 1 : 0;
    }

    // Ws[k][c] with row pitch 68 floats (272B rows, 16B-aligned)
    __shared__ float Ws[128 * 68];
    int tid = threadIdx.x;

    for (int i = tid; i < OUT_C * IN_C; i += 256) {
        int c = i >> 7;
        int k = i & 127;
        Ws[k * 68 + c] = W[i];
    }
    __syncthreads();

    int n = blockIdx.x * 256 + tid;
    if (n >= N_NODES) return;

    float4 acc[16];
#pragma unroll
    for (int i = 0; i < 16; i++) acc[i] = make_float4(0.f, 0.f, 0.f, 0.f);

    const float4* xr = reinterpret_cast<const float4*>(x + (size_t)n * IN_C);

#pragma unroll
    for (int kt = 0; kt < 8; ++kt) {
        float4 xc[4];
#pragma unroll
        for (int i = 0; i < 4; i++) xc[i] = xr[kt * 4 + i];
        const float* xs = reinterpret_cast<const float*>(xc);
#pragma unroll
        for (int kk = 0; kk < 16; ++kk) {
            float xv = xs[kk];
            const float4* wr =
                reinterpret_cast<const float4*>(Ws + (kt * 16 + kk) * 68);
#pragma unroll
            for (int i = 0; i < 16; i++) {
                float4 w = wr[i];
                acc[i].x = fmaf(xv, w.x, acc[i].x);
                acc[i].y = fmaf(xv, w.y, acc[i].y);
                acc[i].z = fmaf(xv, w.z, acc[i].z);
                acc[i].w = fmaf(xv, w.w, acc[i].w);
            }
        }
    }

    float4* ho = reinterpret_cast<float4*>(g_h + (size_t)n * OUT_C);
#pragma unroll
    for (int i = 0; i < 16; i++) ho[i] = acc[i];
}

// ---------------------------------------------------------------------------
// Explicit Batcher odd-even mergesort network for 16 values (63 CEs).
// Literal indices -> guaranteed register allocation + SSA scalarization.
// ---------------------------------------------------------------------------
#define CE(v, i, j)                           \
    {                                         \
        float _lo = fminf(v[i], v[j]);        \
        float _hi = fmaxf(v[i], v[j]);        \
        v[i] = _lo; v[j] = _hi;               \
    }

__device__ __forceinline__ void sort16(float (&v)[16]) {
    CE(v,0,1)  CE(v,2,3)  CE(v,4,5)  CE(v,6,7)  CE(v,8,9)  CE(v,10,11) CE(v,12,13) CE(v,14,15)
    CE(v,0,2)  CE(v,1,3)  CE(v,4,6)  CE(v,5,7)  CE(v,8,10) CE(v,9,11)  CE(v,12,14) CE(v,13,15)
    CE(v,1,2)  CE(v,5,6)  CE(v,9,10) CE(v,13,14)
    CE(v,0,4)  CE(v,1,5)  CE(v,2,6)  CE(v,3,7)  CE(v,8,12) CE(v,9,13)  CE(v,10,14) CE(v,11,15)
    CE(v,2,4)  CE(v,3,5)  CE(v,10,12) CE(v,11,13)
    CE(v,1,2)  CE(v,3,4)  CE(v,5,6)  CE(v,9,10) CE(v,11,12) CE(v,13,14)
    CE(v,0,8)  CE(v,1,9)  CE(v,2,10) CE(v,3,11) CE(v,4,12) CE(v,5,13)  CE(v,6,14)  CE(v,7,15)
    CE(v,4,8)  CE(v,5,9)  CE(v,6,10) CE(v,7,11)
    CE(v,2,4)  CE(v,3,5)  CE(v,6,8)  CE(v,7,9)  CE(v,10,12) CE(v,11,13)
    CE(v,1,2)  CE(v,3,4)  CE(v,5,6)  CE(v,7,8)  CE(v,9,10)  CE(v,11,12) CE(v,13,14)
}

// ---------------------------------------------------------------------------
// Kernel 2: one thread = one (node, channel). Gather the node's 32 neighbor
// rows of h into smem (coalesced float4), sort the two 16-halves in registers,
// then rank-15 of the union = max_i min(a[i], b[15-i]).
// Block = 256 threads = 4 nodes x 64 channels.
// ---------------------------------------------------------------------------
__global__ void __launch_bounds__(256) median_kernel(const void* __restrict__ nbrs,
                                                     float* __restrict__ out) {
    __shared__ float tile[NODES_PER_BLK][KNBR * OUT_C];  // 4 x 8KB
    __shared__ int idx_s[NODES_PER_BLK][KNBR];

    const int tid = threadIdx.x;
    const int w = tid >> 6;       // node slot 0..3
    const int sub = tid & 63;     // 0..63 within node group
    const size_t node = (size_t)blockIdx.x * NODES_PER_BLK + w;

    if (sub < KNBR) {
        long long nb;
        if (g_is64) {
            nb = reinterpret_cast<const long long*>(nbrs)[node * KNBR + sub];
        } else {
            nb = (long long)reinterpret_cast<const int*>(nbrs)[node * KNBR + sub];
        }
        idx_s[w][sub] = (int)nb;
    }
    __syncthreads();

    // cooperative gather: 32 rows x 16 float4 = 512 float4 per node,
    // 8 per thread; 16 consecutive lanes load one 256B row -> coalesced.
    const float4* h4 = reinterpret_cast<const float4*>(g_h);
    float4* t4 = reinterpret_cast<float4*>(tile[w]);
#pragma unroll
    for (int s = 0; s < 8; ++s) {
        int linear = s * 64 + sub;
        int r = linear >> 4;
        int c4 = linear & 15;
        int row = idx_s[w][r];
        t4[r * 16 + c4] = h4[(size_t)row * 16 + c4];
    }
    __syncthreads();

    // column read: lane c reads tile[w][j*64 + c] -> conflict-free
    const int c = sub;
    float a[16], b[16];
#pragma unroll
    for (int j = 0; j < 16; ++j) a[j] = tile[w][j * OUT_C + c];
#pragma unroll
    for (int j = 0; j < 16; ++j) b[j] = tile[w][(j + 16) * OUT_C + c];

    sort16(a);
    sort16(b);

    // rank-15 (lower median) of union of two sorted 16-arrays:
    //   med = max_{i=0..15} min(a[i], b[15-i])     (balanced max tree)
    float m0 = fminf(a[0],  b[15]);
    float m1 = fminf(a[1],  b[14]);
    float m2 = fminf(a[2],  b[13]);
    float m3 = fminf(a[3],  b[12]);
    float m4 = fminf(a[4],  b[11]);
    float m5 = fminf(a[5],  b[10]);
    float m6 = fminf(a[6],  b[9]);
    float m7 = fminf(a[7],  b[8]);
    float m8 = fminf(a[8],  b[7]);
    float m9 = fminf(a[9],  b[6]);
    float m10 = fminf(a[10], b[5]);
    float m11 = fminf(a[11], b[4]);
    float m12 = fminf(a[12], b[3]);
    float m13 = fminf(a[13], b[2]);
    float m14 = fminf(a[14], b[1]);
    float m15 = fminf(a[15], b[0]);

    m0 = fmaxf(m0, m1);   m2 = fmaxf(m2, m3);
    m4 = fmaxf(m4, m5);   m6 = fmaxf(m6, m7);
    m8 = fmaxf(m8, m9);   m10 = fmaxf(m10, m11);
    m12 = fmaxf(m12, m13); m14 = fmaxf(m14, m15);
    m0 = fmaxf(m0, m2);   m4 = fmaxf(m4, m6);
    m8 = fmaxf(m8, m10);  m12 = fmaxf(m12, m14);
    m0 = fmaxf(m0, m4);   m8 = fmaxf(m8, m12);
    m0 = fmaxf(m0, m8);

    out[node * OUT_C + c] = m0;   // coalesced 256B per node group
}

// ---------------------------------------------------------------------------
extern "C" void kernel_launch(void* const* d_in, const int* in_sizes, int n_in,
                              void* d_out, int out_size) {
    // Identify inputs by element count (all three are distinct):
    //   x    : 100000*128 = 12,800,000 f32
    //   W    : 64*128     = 8,192      f32
    //   nbrs : 100000*32  = 3,200,000  (i32 or i64) -- whatever remains
    const float* x = nullptr;
    const float* W = nullptr;
    const void*  nbrs = nullptr;
    for (int i = 0; i < n_in; ++i) {
        if (in_sizes[i] == N_NODES * IN_C)      x = (const float*)d_in[i];
        else if (in_sizes[i] == OUT_C * IN_C)   W = (const float*)d_in[i];
        else                                    nbrs = d_in[i];
    }
    float* out = (float*)d_out;  // [100000, 64] f32

    gemm_kernel<<<(N_NODES + 255) / 256, 256>>>(x, W, (const int*)nbrs);
    median_kernel<<<N_NODES / NODES_PER_BLK, 256>>>(nbrs, out);
}